// round 6
// baseline (speedup 1.0000x reference)
#include <cuda_runtime.h>
#include <cuda_bf16.h>
#include <cstdint>
#include <cstddef>

// Pairwise Euclidean distance, B=8192, K=256, D=3072, fp32.
// out[b,k] = sqrt(max(||x||^2 + ||c||^2 - 2 x.c, eps))
// bf16 mma.sync + ldmatrix, 4-stage SMEM ring, 2-deep LDG register staging,
// BM=64 x BN=128 tiles so TWO CTAs co-reside per SM (latency overlap).

#define BB 8192
#define KK 256
#define DD 3072
#define BM 64
#define BN 128
#define BK 32
#define NT (DD / BK)            // 96 k-tiles
#define NSTAGE 4
#define NTHREADS 256
#define EPS_F 1e-12f

#define ROW_B 80                 // bytes per tile row (32 bf16 + pad): ldmatrix conflict-free
#define ATILE_B (BM * ROW_B)     // 5120
#define BTILE_B (BN * ROW_B)     // 10240
#define STAGE_B (ATILE_B + BTILE_B)          // 15360
#define OFF_XSQ  (NSTAGE * STAGE_B)          // 61440
#define OFF_CSQ  (OFF_XSQ + 512)
#define SMEM_BYTES (OFF_CSQ + 512)           // 62464 -> 2 CTAs/SM

static __device__ __forceinline__ uint32_t s2u(const void* p) {
    uint32_t a;
    asm("{.reg .u64 t; cvta.to.shared.u64 t, %1; cvt.u32.u64 %0, t;}"
        : "=r"(a) : "l"(p));
    return a;
}

#define LDSM_X4(r0, r1, r2, r3, a)                                            \
    asm volatile("ldmatrix.sync.aligned.m8n8.x4.shared.b16 {%0,%1,%2,%3}, [%4];" \
                 : "=r"(r0), "=r"(r1), "=r"(r2), "=r"(r3) : "r"(a))

__global__ void __launch_bounds__(NTHREADS, 2)
rbf_2cta_kernel(const float* __restrict__ X, const float* __restrict__ C,
                float* __restrict__ out)
{
    extern __shared__ __align__(16) char smem[];
    const uint32_t sb = s2u(smem);
    const int tid  = threadIdx.x;
    const int wid  = tid >> 5;
    const int lane = tid & 31;
    const int bm = blockIdx.y;
    const int bn = blockIdx.x;

    if (tid < 64)  ((float*)(smem + OFF_XSQ))[tid] = 0.f;
    if (tid < 128) ((float*)(smem + OFF_CSQ))[tid] = 0.f;

    // -------- producer mapping --------
    // A: 64 rows x 8 float4 = 512 chunks -> thread t handles {t, t+256}
    // B: 128 rows x 8 float4 = 1024 chunks -> thread t handles {t, t+256, t+512, t+768}
    const int lr = tid >> 3;     // 0..31 (base row)
    const int c4 = tid & 7;      // float4 column within 32-float k-row
    const float4* gA = reinterpret_cast<const float4*>(X + (size_t)(bm * BM) * DD);
    const float4* gB = reinterpret_cast<const float4*>(C + (size_t)(bn * BN) * DD);
    const int row4 = DD / 4;     // 768

    float4 ra[2][2], rb[2][4];
    float xs[2] = {0.f, 0.f};
    float cs[4] = {0.f, 0.f, 0.f, 0.f};

    auto ldg_tile = [&](int kt, int buf) {
        const int k4 = kt * (BK / 4);
        #pragma unroll
        for (int p = 0; p < 2; p++)
            ra[buf][p] = gA[(size_t)(p * 32 + lr) * row4 + k4 + c4];
        #pragma unroll
        for (int p = 0; p < 4; p++)
            rb[buf][p] = gB[(size_t)(p * 32 + lr) * row4 + k4 + c4];
    };

    auto sts_tile = [&](int kt, int buf) {
        const int s = kt & (NSTAGE - 1);
        const uint32_t base = sb + (uint32_t)s * STAGE_B;
        #pragma unroll
        for (int p = 0; p < 2; p++) {
            const uint32_t off = (uint32_t)(p * 32 + lr) * ROW_B + (uint32_t)c4 * 8;
            float4 v = ra[buf][p];
            xs[p] += v.x * v.x + v.y * v.y + v.z * v.z + v.w * v.w;
            __nv_bfloat162 q0 = __float22bfloat162_rn(make_float2(v.x, v.y));
            __nv_bfloat162 q1 = __float22bfloat162_rn(make_float2(v.z, v.w));
            asm volatile("st.shared.v2.b32 [%0], {%1,%2};"
                         :: "r"(base + off),
                            "r"(*reinterpret_cast<uint32_t*>(&q0)),
                            "r"(*reinterpret_cast<uint32_t*>(&q1)) : "memory");
        }
        #pragma unroll
        for (int p = 0; p < 4; p++) {
            const uint32_t off = (uint32_t)(p * 32 + lr) * ROW_B + (uint32_t)c4 * 8;
            float4 v = rb[buf][p];
            cs[p] += v.x * v.x + v.y * v.y + v.z * v.z + v.w * v.w;
            __nv_bfloat162 q0 = __float22bfloat162_rn(make_float2(v.x, v.y));
            __nv_bfloat162 q1 = __float22bfloat162_rn(make_float2(v.z, v.w));
            asm volatile("st.shared.v2.b32 [%0], {%1,%2};"
                         :: "r"(base + (uint32_t)ATILE_B + off),
                            "r"(*reinterpret_cast<uint32_t*>(&q0)),
                            "r"(*reinterpret_cast<uint32_t*>(&q1)) : "memory");
        }
    };

    // -------- compute mapping: 2(M) x 4(N) warp grid, warp tile 32x32 --------
    const int wm = wid & 1;
    const int wn = wid >> 1;
    const int fr = lane >> 2;
    const int fc = (lane & 3) * 2;
    const int g  = lane >> 3;
    const int ri = lane & 7;
    const uint32_t lm_off = (uint32_t)(((g & 1) * 8 + ri) * ROW_B + (g >> 1) * 16);

    float acc[2][4][4];
    #pragma unroll
    for (int i = 0; i < 2; i++)
        #pragma unroll
        for (int j = 0; j < 4; j++)
            #pragma unroll
            for (int q = 0; q < 4; q++) acc[i][j][q] = 0.f;

    // -------- prologue: ldg(k) lands in buf[(k+1)&1]; stages 0..2 filled --------
    ldg_tile(0, 1);
    ldg_tile(1, 0);
    sts_tile(0, 1);
    ldg_tile(2, 1);
    sts_tile(1, 0);
    ldg_tile(3, 0);
    sts_tile(2, 1);
    ldg_tile(4, 1);
    __syncthreads();

    // -------- mainloop: mma(kt); sts(kt+3); ldg(kt+5); sync --------
    #pragma unroll 1
    for (int kt = 0; kt < NT; kt++) {
        const uint32_t stA = sb + (uint32_t)(kt & (NSTAGE - 1)) * STAGE_B;
        const uint32_t stB = stA + ATILE_B;

        #pragma unroll
        for (int ks = 0; ks < 2; ks++) {
            const uint32_t kof = (uint32_t)ks * 32;   // 16 bf16 = 32B
            uint32_t a[2][4], b[2][4];
            #pragma unroll
            for (int im = 0; im < 2; im++) {
                const uint32_t ad = stA + (uint32_t)((wm * 32 + im * 16) * ROW_B)
                                        + kof + lm_off;
                LDSM_X4(a[im][0], a[im][1], a[im][2], a[im][3], ad);
            }
            #pragma unroll
            for (int jb = 0; jb < 2; jb++) {
                const uint32_t bd = stB + (uint32_t)((wn * 32 + jb * 16) * ROW_B)
                                        + kof + lm_off;
                LDSM_X4(b[jb][0], b[jb][1], b[jb][2], b[jb][3], bd);
            }
            #pragma unroll
            for (int im = 0; im < 2; im++)
                #pragma unroll
                for (int j = 0; j < 4; j++) {
                    const int jb = j >> 1, p = j & 1;
                    asm volatile(
                        "mma.sync.aligned.m16n8k16.row.col.f32.bf16.bf16.f32 "
                        "{%0,%1,%2,%3}, {%4,%5,%6,%7}, {%8,%9}, {%0,%1,%2,%3};\n"
                        : "+f"(acc[im][j][0]), "+f"(acc[im][j][1]),
                          "+f"(acc[im][j][2]), "+f"(acc[im][j][3])
                        : "r"(a[im][0]), "r"(a[im][1]), "r"(a[im][2]), "r"(a[im][3]),
                          "r"(b[jb][p]), "r"(b[jb][p + 2]));
                }
        }

        if (kt + 3 < NT) sts_tile(kt + 3, kt & 1);
        if (kt + 5 < NT) ldg_tile(kt + 5, kt & 1);
        __syncthreads();
    }

    // -------- norms: shared atomics (8-way max contention) --------
    #pragma unroll
    for (int p = 0; p < 2; p++)
        atomicAdd(&((float*)(smem + OFF_XSQ))[p * 32 + lr], xs[p]);
    #pragma unroll
    for (int p = 0; p < 4; p++)
        atomicAdd(&((float*)(smem + OFF_CSQ))[p * 32 + lr], cs[p]);
    __syncthreads();

    // -------- epilogue: dist = sqrt(max(xsq + csq - 2*cross, eps)) --------
    const float* xsq = (const float*)(smem + OFF_XSQ);
    const float* csq = (const float*)(smem + OFF_CSQ);
    #pragma unroll
    for (int i = 0; i < 2; i++) {
        const int row_l0 = wm * 32 + i * 16 + fr;
        #pragma unroll
        for (int hf = 0; hf < 2; hf++) {
            const int row_l = row_l0 + hf * 8;
            const float xq = xsq[row_l];
            float* orow = out + ((size_t)bm * BM + row_l) * KK + bn * BN;
            #pragma unroll
            for (int j = 0; j < 4; j++) {
                const int col_l = wn * 32 + j * 8 + fc;
                const float d0 = sqrtf(fmaxf(
                    xq + csq[col_l] - 2.f * acc[i][j][hf * 2 + 0], EPS_F));
                const float d1 = sqrtf(fmaxf(
                    xq + csq[col_l + 1] - 2.f * acc[i][j][hf * 2 + 1], EPS_F));
                *reinterpret_cast<float2*>(orow + col_l) = make_float2(d0, d1);
            }
        }
    }
}

extern "C" void kernel_launch(void* const* d_in, const int* in_sizes, int n_in,
                              void* d_out, int out_size)
{
    const float* X = (const float*)d_in[0];   // inputs  [8192, 3072] fp32
    const float* C = (const float*)d_in[1];   // centers [256, 3072]  fp32
    float* out = (float*)d_out;               // [8192, 256] fp32

    cudaFuncSetAttribute(rbf_2cta_kernel,
                         cudaFuncAttributeMaxDynamicSharedMemorySize, SMEM_BYTES);
    dim3 grid(KK / BN, BB / BM);              // (2, 128) = 256 CTAs, 2 per SM
    rbf_2cta_kernel<<<grid, NTHREADS, SMEM_BYTES>>>(X, C, out);
}

// round 7
// speedup vs baseline: 2.3503x; 2.3503x over previous
#include <cuda_runtime.h>
#include <cuda_bf16.h>
#include <cstdint>
#include <cstddef>

// Pairwise Euclidean distance, B=8192, K=256, D=3072, fp32.
// out[b,k] = sqrt(max(||x||^2 + ||c||^2 - 2 x.c, eps))
// Kernel 1: convert centers fp32->bf16 (+csq).  Kernel 2: bf16 mma.sync GEMM,
// 512 threads, split-k warp groups, cp.async B tiles, 6-stage ring.

#define BB 8192
#define KK 256
#define DD 3072
#define BM 128
#define BN 128
#define BK 32
#define NT (DD / BK)            // 96 k-tiles
#define NPAIR (NT / 2)          // 48 pairs
#define RING 6                  // k-tile stages
#define NTHREADS 512
#define EPS_F 1e-12f

#define ROW_B 80                // 32 bf16 + 16B pad: ldmatrix conflict-free
#define TILE_B (128 * ROW_B)    // 10240 per operand per k-stage
#define STAGE_B (2 * TILE_B)    // 20480 (A then B)
#define RING_B (RING * STAGE_B) // 122880
#define OFF_XSQ  RING_B
#define OFF_CSQ  (OFF_XSQ + 512)
#define SMEM_BYTES (OFF_CSQ + 512)   // 123904
#define STASH_STRIDE 132        // epilogue acc stash (floats per row)

__device__ __nv_bfloat16 g_cb[KK * DD];   // centers in bf16
__device__ float g_csq[KK];               // ||c||^2 fp32

static __device__ __forceinline__ uint32_t s2u(const void* p) {
    uint32_t a;
    asm("{.reg .u64 t; cvta.to.shared.u64 t, %1; cvt.u32.u64 %0, t;}"
        : "=r"(a) : "l"(p));
    return a;
}

#define LDSM_X4(r0, r1, r2, r3, a)                                            \
    asm volatile("ldmatrix.sync.aligned.m8n8.x4.shared.b16 {%0,%1,%2,%3}, [%4];" \
                 : "=r"(r0), "=r"(r1), "=r"(r2), "=r"(r3) : "r"(a))

// ---------------- prepass: centers fp32 -> bf16, csq ----------------
__global__ void __launch_bounds__(128, 8)
prep_c_kernel(const float* __restrict__ C)
{
    const int row = blockIdx.x;              // 0..255
    const float4* src = reinterpret_cast<const float4*>(C + (size_t)row * DD);
    uint2* dst = reinterpret_cast<uint2*>(g_cb + (size_t)row * DD);
    float s = 0.f;
    #pragma unroll
    for (int i = 0; i < 6; i++) {
        const int q = threadIdx.x + i * 128;  // 768 float4 per row
        float4 v = src[q];
        s += v.x * v.x + v.y * v.y + v.z * v.z + v.w * v.w;
        __nv_bfloat162 p0 = __float22bfloat162_rn(make_float2(v.x, v.y));
        __nv_bfloat162 p1 = __float22bfloat162_rn(make_float2(v.z, v.w));
        uint2 u;
        u.x = *reinterpret_cast<uint32_t*>(&p0);
        u.y = *reinterpret_cast<uint32_t*>(&p1);
        dst[q] = u;
    }
    // block reduce (4 warps)
    #pragma unroll
    for (int o = 16; o > 0; o >>= 1)
        s += __shfl_xor_sync(0xFFFFFFFFu, s, o);
    __shared__ float red[4];
    if ((threadIdx.x & 31) == 0) red[threadIdx.x >> 5] = s;
    __syncthreads();
    if (threadIdx.x == 0)
        g_csq[row] = red[0] + red[1] + red[2] + red[3];
}

// ---------------- main GEMM ----------------
__global__ void __launch_bounds__(NTHREADS, 1)
rbf_sk_kernel(const float* __restrict__ X, float* __restrict__ out)
{
    extern __shared__ __align__(16) char smem[];
    const uint32_t sb = s2u(smem);
    const int tid  = threadIdx.x;
    const int wid  = tid >> 5;
    const int lane = tid & 31;
    const int bm = blockIdx.y;
    const int bn = blockIdx.x;

    float* xsq_s = (float*)(smem + OFF_XSQ);
    float* csq_s = (float*)(smem + OFF_CSQ);
    if (tid < 128) {
        xsq_s[tid] = 0.f;
        csq_s[tid] = g_csq[bn * BN + tid];
    }

    // ---- A producer mapping: 4 float4/thread/pair (2 per k-tile) ----
    // q = tid + 512*j, j=0..3: tile=(j>>1), row=((tid>>3)+64*(j&1)), c4=tid&7
    const int r0 = tid >> 3;                 // 0..63
    const int c4 = tid & 7;
    const float* gA = X + (size_t)(bm * BM) * DD;
    float4 ra[4];
    float xs0 = 0.f, xs1 = 0.f;

    auto ldgA = [&](int p) {                 // loads pair p (k-tiles 2p, 2p+1)
        #pragma unroll
        for (int j = 0; j < 4; j++) {
            const int row = r0 + 64 * (j & 1);
            const int kt  = 2 * p + (j >> 1);
            ra[j] = *reinterpret_cast<const float4*>(
                gA + (size_t)row * DD + kt * BK + c4 * 4);
        }
    };
    auto stsA = [&](int p) {
        #pragma unroll
        for (int j = 0; j < 4; j++) {
            const int row = r0 + 64 * (j & 1);
            const int kt  = 2 * p + (j >> 1);
            const int s   = kt % RING;
            float4 v = ra[j];
            const float nq = v.x * v.x + v.y * v.y + v.z * v.z + v.w * v.w;
            if (j & 1) xs1 += nq; else xs0 += nq;
            __nv_bfloat162 q0 = __float22bfloat162_rn(make_float2(v.x, v.y));
            __nv_bfloat162 q1 = __float22bfloat162_rn(make_float2(v.z, v.w));
            asm volatile("st.shared.v2.b32 [%0], {%1,%2};"
                         :: "r"(sb + (uint32_t)s * STAGE_B
                               + (uint32_t)row * ROW_B + (uint32_t)c4 * 8),
                            "r"(*reinterpret_cast<uint32_t*>(&q0)),
                            "r"(*reinterpret_cast<uint32_t*>(&q1)) : "memory");
        }
    };

    // ---- B producer: cp.async bf16, 2 chunks/thread/pair ----
    const int brow = tid >> 2;               // 0..127
    const int bc   = tid & 3;                // 16B chunk
    const __nv_bfloat16* gB = g_cb + (size_t)(bn * BN + brow) * DD + bc * 8;
    auto cpB = [&](int p) {
        #pragma unroll
        for (int h = 0; h < 2; h++) {        // k-tiles 2p, 2p+1
            const int kt = 2 * p + h;
            const int s  = kt % RING;
            const uint32_t dst = sb + (uint32_t)s * STAGE_B + TILE_B
                               + (uint32_t)brow * ROW_B + (uint32_t)bc * 16;
            asm volatile("cp.async.cg.shared.global [%0], [%1], 16;"
                         :: "r"(dst), "l"(gB + kt * BK) : "memory");
        }
        asm volatile("cp.async.commit_group;" ::: "memory");
    };

    // ---- compute mapping: split-k groups, warp tile 32x64 ----
    const int wk = wid >> 3;                 // k-parity group 0/1
    const int w8 = wid & 7;
    const int wm = w8 & 3;                   // 4 in M (32 rows)
    const int wn = w8 >> 2;                  // 2 in N (64 cols)
    const int fr = lane >> 2;
    const int fc = (lane & 3) * 2;
    const int g  = lane >> 3;
    const int ri = lane & 7;
    const uint32_t lm_off = (uint32_t)(((g & 1) * 8 + ri) * ROW_B + (g >> 1) * 16);

    float acc[2][8][4];
    #pragma unroll
    for (int i = 0; i < 2; i++)
        #pragma unroll
        for (int j = 0; j < 8; j++)
            #pragma unroll
            for (int q = 0; q < 4; q++) acc[i][j][q] = 0.f;

    // ---- prologue ----
    ldgA(0);
    cpB(0);
    stsA(0);
    ldgA(1);
    cpB(1);
    asm volatile("cp.async.wait_group 1;" ::: "memory");   // B(pair 0) done
    __syncthreads();

    // ---- mainloop over pairs ----
    #pragma unroll 1
    for (int p = 0; p < NPAIR; p++) {
        const int kt = 2 * p + wk;           // my group's tile
        const uint32_t stA = sb + (uint32_t)(kt % RING) * STAGE_B;
        const uint32_t stB = stA + TILE_B;

        #pragma unroll
        for (int ks = 0; ks < 2; ks++) {
            const uint32_t kof = (uint32_t)ks * 32;
            uint32_t a[2][4], b[4][4];
            #pragma unroll
            for (int im = 0; im < 2; im++) {
                const uint32_t ad = stA + (uint32_t)((wm * 32 + im * 16) * ROW_B)
                                        + kof + lm_off;
                LDSM_X4(a[im][0], a[im][1], a[im][2], a[im][3], ad);
            }
            #pragma unroll
            for (int jb = 0; jb < 4; jb++) {
                const uint32_t bd = stB + (uint32_t)((wn * 64 + jb * 16) * ROW_B)
                                        + kof + lm_off;
                LDSM_X4(b[jb][0], b[jb][1], b[jb][2], b[jb][3], bd);
            }
            #pragma unroll
            for (int im = 0; im < 2; im++)
                #pragma unroll
                for (int j = 0; j < 8; j++) {
                    const int jb = j >> 1, pp = j & 1;
                    asm volatile(
                        "mma.sync.aligned.m16n8k16.row.col.f32.bf16.bf16.f32 "
                        "{%0,%1,%2,%3}, {%4,%5,%6,%7}, {%8,%9}, {%0,%1,%2,%3};\n"
                        : "+f"(acc[im][j][0]), "+f"(acc[im][j][1]),
                          "+f"(acc[im][j][2]), "+f"(acc[im][j][3])
                        : "r"(a[im][0]), "r"(a[im][1]), "r"(a[im][2]), "r"(a[im][3]),
                          "r"(b[jb][pp]), "r"(b[jb][pp + 2]));
                }
        }

        if (p + 1 < NPAIR) {
            stsA(p + 1);
            if (p + 2 < NPAIR) {
                ldgA(p + 2);
                cpB(p + 2);
                asm volatile("cp.async.wait_group 1;" ::: "memory");
            } else {
                asm volatile("cp.async.wait_group 0;" ::: "memory");
            }
        }
        __syncthreads();
    }

    // ---- norms ----
    atomicAdd(&xsq_s[r0], xs0);
    atomicAdd(&xsq_s[r0 + 64], xs1);
    __syncthreads();

    // ---- split-k merge via SMEM stash + fused epilogue ----
    float* stash = (float*)smem;             // [128][STASH_STRIDE]
    if (wk == 1) {
        #pragma unroll
        for (int im = 0; im < 2; im++)
            #pragma unroll
            for (int hf = 0; hf < 2; hf++) {
                const int row = wm * 32 + im * 16 + hf * 8 + fr;
                #pragma unroll
                for (int j = 0; j < 8; j++) {
                    const int col = wn * 64 + j * 8 + fc;
                    *reinterpret_cast<float2*>(&stash[row * STASH_STRIDE + col]) =
                        make_float2(acc[im][j][hf * 2], acc[im][j][hf * 2 + 1]);
                }
            }
    }
    __syncthreads();
    if (wk == 0) {
        #pragma unroll
        for (int im = 0; im < 2; im++)
            #pragma unroll
            for (int hf = 0; hf < 2; hf++) {
                const int row = wm * 32 + im * 16 + hf * 8 + fr;
                const float xq = xsq_s[row];
                float* orow = out + ((size_t)bm * BM + row) * KK + bn * BN;
                #pragma unroll
                for (int j = 0; j < 8; j++) {
                    const int col = wn * 64 + j * 8 + fc;
                    const float2 o = *reinterpret_cast<const float2*>(
                        &stash[row * STASH_STRIDE + col]);
                    const float cr0 = acc[im][j][hf * 2] + o.x;
                    const float cr1 = acc[im][j][hf * 2 + 1] + o.y;
                    const float d0 = sqrtf(fmaxf(xq + csq_s[col] - 2.f * cr0, EPS_F));
                    const float d1 = sqrtf(fmaxf(xq + csq_s[col + 1] - 2.f * cr1, EPS_F));
                    *reinterpret_cast<float2*>(orow + col) = make_float2(d0, d1);
                }
            }
    }
}

extern "C" void kernel_launch(void* const* d_in, const int* in_sizes, int n_in,
                              void* d_out, int out_size)
{
    const float* X = (const float*)d_in[0];   // inputs  [8192, 3072] fp32
    const float* C = (const float*)d_in[1];   // centers [256, 3072]  fp32
    float* out = (float*)d_out;               // [8192, 256] fp32

    prep_c_kernel<<<KK, 128>>>(C);

    cudaFuncSetAttribute(rbf_sk_kernel,
                         cudaFuncAttributeMaxDynamicSharedMemorySize, SMEM_BYTES);
    dim3 grid(KK / BN, BB / BM);              // (2, 64) = 128 CTAs
    rbf_sk_kernel<<<grid, NTHREADS, SMEM_BYTES>>>(X, out);
}

// round 8
// speedup vs baseline: 2.5560x; 1.0875x over previous
#include <cuda_runtime.h>
#include <cuda_bf16.h>
#include <cstdint>
#include <cstddef>

// Pairwise Euclidean distance, B=8192, K=256, D=3072, fp32.
// out[b,k] = sqrt(max(||x||^2 + ||c||^2 - 2 x.c, eps))
// Prepass: centers fp32->bf16 + csq. Main: bf16 mma.sync GEMM, 512 threads
// split into TWO independent 256-thread k-parity pipelines (own named barrier,
// own 4-stage subring, own producers) -> phase-drift latency overlap.

#define BB 8192
#define KK 256
#define DD 3072
#define BM 128
#define BN 128
#define BK 32
#define NT (DD / BK)            // 96 k-tiles
#define NTG (NT / 2)            // 48 tiles per group
#define NTHREADS 512
#define EPS_F 1e-12f

#define ROW_B 80                // 32 bf16 + 16B pad: ldmatrix conflict-free
#define TILE_B (128 * ROW_B)    // 10240 per operand
#define STAGE_B (2 * TILE_B)    // 20480 (A then B)
#define NSTAGE 8                // global ring; 4 per parity group
#define OFF_XSQ  (NSTAGE * STAGE_B)          // 163840
#define OFF_CSQ  (OFF_XSQ + 512)
#define SMEM_BYTES (OFF_CSQ + 512)           // 164864
#define STASH_STRIDE 132        // epilogue stash floats/row (reuses ring smem)

__device__ __nv_bfloat16 g_cb[KK * DD];   // centers bf16
__device__ float g_csq[KK];               // ||c||^2

static __device__ __forceinline__ uint32_t s2u(const void* p) {
    uint32_t a;
    asm("{.reg .u64 t; cvta.to.shared.u64 t, %1; cvt.u32.u64 %0, t;}"
        : "=r"(a) : "l"(p));
    return a;
}

#define LDSM_X4(r0, r1, r2, r3, a)                                            \
    asm volatile("ldmatrix.sync.aligned.m8n8.x4.shared.b16 {%0,%1,%2,%3}, [%4];" \
                 : "=r"(r0), "=r"(r1), "=r"(r2), "=r"(r3) : "r"(a))

#define GBAR(id)                                                              \
    asm volatile("bar.sync %0, 256;" :: "r"(id) : "memory")

// ---------------- prepass: centers fp32 -> bf16, csq ----------------
__global__ void __launch_bounds__(128, 8)
prep_c_kernel(const float* __restrict__ C)
{
    const int row = blockIdx.x;
    const float4* src = reinterpret_cast<const float4*>(C + (size_t)row * DD);
    uint2* dst = reinterpret_cast<uint2*>(g_cb + (size_t)row * DD);
    float s = 0.f;
    #pragma unroll
    for (int i = 0; i < 6; i++) {
        const int q = threadIdx.x + i * 128;
        float4 v = src[q];
        s += v.x * v.x + v.y * v.y + v.z * v.z + v.w * v.w;
        __nv_bfloat162 p0 = __float22bfloat162_rn(make_float2(v.x, v.y));
        __nv_bfloat162 p1 = __float22bfloat162_rn(make_float2(v.z, v.w));
        uint2 u;
        u.x = *reinterpret_cast<uint32_t*>(&p0);
        u.y = *reinterpret_cast<uint32_t*>(&p1);
        dst[q] = u;
    }
    #pragma unroll
    for (int o = 16; o > 0; o >>= 1)
        s += __shfl_xor_sync(0xFFFFFFFFu, s, o);
    __shared__ float red[4];
    if ((threadIdx.x & 31) == 0) red[threadIdx.x >> 5] = s;
    __syncthreads();
    if (threadIdx.x == 0)
        g_csq[row] = red[0] + red[1] + red[2] + red[3];
}

// ---------------- main GEMM ----------------
__global__ void __launch_bounds__(NTHREADS, 1)
rbf_dual_kernel(const float* __restrict__ X, float* __restrict__ out)
{
    extern __shared__ __align__(16) char smem[];
    const uint32_t sb = s2u(smem);
    const int tid  = threadIdx.x;
    const int wid  = tid >> 5;
    const int lane = tid & 31;
    const int bm = blockIdx.y;
    const int bn = blockIdx.x;

    const int g   = wid >> 3;          // k-parity group 0/1
    const int gt  = tid & 255;         // thread id within group
    const int bar = g + 1;             // named barrier id

    float* xsq_s = (float*)(smem + OFF_XSQ);
    float* csq_s = (float*)(smem + OFF_CSQ);
    if (tid < 128) {
        xsq_s[tid] = 0.f;
        csq_s[tid] = g_csq[bn * BN + tid];
    }
    __syncthreads();

    // group stage base: tile i (group-local, global kt=2i+g) -> stage g + 2*(i&3)
    const uint32_t sbg = sb + (uint32_t)g * STAGE_B;

    // ---- A producer (per group): 4 chunks/thread/tile ----
    const int ar = gt >> 3;            // base row 0..31 (rows ar+32j)
    const int c4 = gt & 7;
    const float* gA = X + (size_t)(bm * BM) * DD;
    float4 ra[4];
    float xs[4] = {0.f, 0.f, 0.f, 0.f};

    auto ldgA = [&](int i) {           // tile i -> kt = 2i+g
        const int kt = 2 * i + g;
        #pragma unroll
        for (int j = 0; j < 4; j++)
            ra[j] = *reinterpret_cast<const float4*>(
                gA + (size_t)(ar + 32 * j) * DD + kt * BK + c4 * 4);
    };
    auto stsA = [&](int i) {
        const uint32_t base = sbg + (uint32_t)(i & 3) * (2 * STAGE_B);
        #pragma unroll
        for (int j = 0; j < 4; j++) {
            float4 v = ra[j];
            xs[j] += v.x * v.x + v.y * v.y + v.z * v.z + v.w * v.w;
            __nv_bfloat162 q0 = __float22bfloat162_rn(make_float2(v.x, v.y));
            __nv_bfloat162 q1 = __float22bfloat162_rn(make_float2(v.z, v.w));
            asm volatile("st.shared.v2.b32 [%0], {%1,%2};"
                         :: "r"(base + (uint32_t)(ar + 32 * j) * ROW_B
                               + (uint32_t)c4 * 8),
                            "r"(*reinterpret_cast<uint32_t*>(&q0)),
                            "r"(*reinterpret_cast<uint32_t*>(&q1)) : "memory");
        }
    };

    // ---- B producer (per group): cp.async, 2 chunks/thread/tile ----
    const int br = gt >> 2;            // rows br, br+64
    const int bc = gt & 3;             // 16B chunk in 64B row
    const __nv_bfloat16* gB = g_cb + (size_t)(bn * BN) * DD;
    auto cpB = [&](int i) {
        const int kt = 2 * i + g;
        const uint32_t base = sbg + (uint32_t)(i & 3) * (2 * STAGE_B) + TILE_B;
        #pragma unroll
        for (int h = 0; h < 2; h++) {
            const int row = br + 64 * h;
            const uint32_t dst = base + (uint32_t)row * ROW_B + (uint32_t)bc * 16;
            asm volatile("cp.async.cg.shared.global [%0], [%1], 16;"
                         :: "r"(dst),
                            "l"(gB + (size_t)row * DD + kt * BK + bc * 8) : "memory");
        }
        asm volatile("cp.async.commit_group;" ::: "memory");
    };

    // ---- compute mapping: per group 4(M)x2(N) warps, warp tile 32x64 ----
    const int w8 = wid & 7;
    const int wm = w8 & 3;
    const int wn = w8 >> 2;
    const int fr = lane >> 2;
    const int fc = (lane & 3) * 2;
    const int lg = lane >> 3;
    const int ri = lane & 7;
    const uint32_t lm_off = (uint32_t)(((lg & 1) * 8 + ri) * ROW_B + (lg >> 1) * 16);

    float acc[2][8][4];
    #pragma unroll
    for (int i = 0; i < 2; i++)
        #pragma unroll
        for (int j = 0; j < 8; j++)
            #pragma unroll
            for (int q = 0; q < 4; q++) acc[i][j][q] = 0.f;

    // ---- prologue (group-local) ----
    ldgA(0);
    cpB(0);
    stsA(0);
    ldgA(1);
    cpB(1);
    asm volatile("cp.async.wait_group 1;" ::: "memory");
    GBAR(bar);

    // ---- mainloop: 48 group-local tiles ----
    #pragma unroll 1
    for (int i = 0; i < NTG; i++) {
        const uint32_t stA = sbg + (uint32_t)(i & 3) * (2 * STAGE_B);
        const uint32_t stB = stA + TILE_B;

        #pragma unroll
        for (int ks = 0; ks < 2; ks++) {
            const uint32_t kof = (uint32_t)ks * 32;
            uint32_t a[2][4], b[4][4];
            #pragma unroll
            for (int im = 0; im < 2; im++) {
                const uint32_t ad = stA + (uint32_t)((wm * 32 + im * 16) * ROW_B)
                                        + kof + lm_off;
                LDSM_X4(a[im][0], a[im][1], a[im][2], a[im][3], ad);
            }
            #pragma unroll
            for (int jb = 0; jb < 4; jb++) {
                const uint32_t bd = stB + (uint32_t)((wn * 64 + jb * 16) * ROW_B)
                                        + kof + lm_off;
                LDSM_X4(b[jb][0], b[jb][1], b[jb][2], b[jb][3], bd);
            }
            #pragma unroll
            for (int im = 0; im < 2; im++)
                #pragma unroll
                for (int j = 0; j < 8; j++) {
                    const int jb = j >> 1, pp = j & 1;
                    asm volatile(
                        "mma.sync.aligned.m16n8k16.row.col.f32.bf16.bf16.f32 "
                        "{%0,%1,%2,%3}, {%4,%5,%6,%7}, {%8,%9}, {%0,%1,%2,%3};\n"
                        : "+f"(acc[im][j][0]), "+f"(acc[im][j][1]),
                          "+f"(acc[im][j][2]), "+f"(acc[im][j][3])
                        : "r"(a[im][0]), "r"(a[im][1]), "r"(a[im][2]), "r"(a[im][3]),
                          "r"(b[jb][pp]), "r"(b[jb][pp + 2]));
                }
        }

        if (i + 1 < NTG) {
            stsA(i + 1);
            if (i + 2 < NTG) {
                ldgA(i + 2);
                cpB(i + 2);
                asm volatile("cp.async.wait_group 1;" ::: "memory");
            } else {
                asm volatile("cp.async.wait_group 0;" ::: "memory");
            }
        }
        GBAR(bar);
    }

    // ---- norms: both groups contribute (k split across groups) ----
    #pragma unroll
    for (int j = 0; j < 4; j++)
        atomicAdd(&xsq_s[ar + 32 * j], xs[j]);
    __syncthreads();                    // both groups done; ring now reusable

    // ---- split-k merge + fused epilogue ----
    float* stash = (float*)smem;        // [128][STASH_STRIDE]
    if (g == 1) {
        #pragma unroll
        for (int im = 0; im < 2; im++)
            #pragma unroll
            for (int hf = 0; hf < 2; hf++) {
                const int row = wm * 32 + im * 16 + hf * 8 + fr;
                #pragma unroll
                for (int j = 0; j < 8; j++) {
                    const int col = wn * 64 + j * 8 + fc;
                    *reinterpret_cast<float2*>(&stash[row * STASH_STRIDE + col]) =
                        make_float2(acc[im][j][hf * 2], acc[im][j][hf * 2 + 1]);
                }
            }
    }
    __syncthreads();
    if (g == 0) {
        #pragma unroll
        for (int im = 0; im < 2; im++)
            #pragma unroll
            for (int hf = 0; hf < 2; hf++) {
                const int row = wm * 32 + im * 16 + hf * 8 + fr;
                const float xq = xsq_s[row];
                float* orow = out + ((size_t)bm * BM + row) * KK + bn * BN;
                #pragma unroll
                for (int j = 0; j < 8; j++) {
                    const int col = wn * 64 + j * 8 + fc;
                    const float2 o = *reinterpret_cast<const float2*>(
                        &stash[row * STASH_STRIDE + col]);
                    const float cr0 = acc[im][j][hf * 2] + o.x;
                    const float cr1 = acc[im][j][hf * 2 + 1] + o.y;
                    const float d0 = sqrtf(fmaxf(xq + csq_s[col] - 2.f * cr0, EPS_F));
                    const float d1 = sqrtf(fmaxf(xq + csq_s[col + 1] - 2.f * cr1, EPS_F));
                    *reinterpret_cast<float2*>(orow + col) = make_float2(d0, d1);
                }
            }
    }
}

extern "C" void kernel_launch(void* const* d_in, const int* in_sizes, int n_in,
                              void* d_out, int out_size)
{
    const float* X = (const float*)d_in[0];   // inputs  [8192, 3072] fp32
    const float* C = (const float*)d_in[1];   // centers [256, 3072]  fp32
    float* out = (float*)d_out;               // [8192, 256] fp32

    prep_c_kernel<<<KK, 128>>>(C);

    cudaFuncSetAttribute(rbf_dual_kernel,
                         cudaFuncAttributeMaxDynamicSharedMemorySize, SMEM_BYTES);
    dim3 grid(KK / BN, BB / BM);              // (2, 64) = 128 CTAs
    rbf_dual_kernel<<<grid, NTHREADS, SMEM_BYTES>>>(X, out);
}